// round 4
// baseline (speedup 1.0000x reference)
#include <cuda_runtime.h>
#include <cstddef>

#define TT 1024
#define BB 16
#define CC 64
#define NW 8              // warps per dp CTA
#define RPL 4             // rows per lane (NW * 32 * RPL == TT)
#define CHW 8             // boundary flag chunk (columns)
#define BIGF 1e10f
// 1/(gamma*ln2), gamma = 0.01
#define KS 144.2695040888963f
// gamma*ln2
#define GLN2 0.006931471805599453f
// exp2(-KS*g) < 2^-18 for g > 0.125 -> softmin == min to ~1e-7
#define GAP_THRESH 0.125f

// Scratch (device globals: allocation-free rule)
__device__ float g_cost[(size_t)BB * TT * TT];   // 64 MB, row-major per batch
__device__ float g_nx[BB * TT];
__device__ float g_ny[BB * TT];
__device__ float g_partial[BB];

__device__ __forceinline__ float ex2f(float x) {
    float y;
    asm("ex2.approx.ftz.f32 %0, %1;" : "=f"(y) : "f"(x));
    return y;
}
__device__ __forceinline__ float lg2f(float x) {
    float y;
    asm("lg2.approx.ftz.f32 %0, %1;" : "=f"(y) : "f"(x));
    return y;
}
__device__ __forceinline__ int ld_acq_cta(const int* p) {
    int v;
    asm volatile("ld.acquire.cta.b32 %0, [%1];" : "=r"(v) : "l"(p) : "memory");
    return v;
}
__device__ __forceinline__ void st_rel_cta(int* p, int v) {
    asm volatile("st.release.cta.b32 [%0], %1;" :: "l"(p), "r"(v) : "memory");
}

// ---------------------------------------------------------------------------
// Kernel 0: row norms  ||x_i||^2, ||y_j||^2  (one warp per row)
// ---------------------------------------------------------------------------
__global__ void norms_kernel(const float* __restrict__ x,
                             const float* __restrict__ y) {
    int gwarp = (blockIdx.x * blockDim.x + threadIdx.x) >> 5;
    int lane = threadIdx.x & 31;
    const int nrows = BB * TT;
    if (gwarp >= 2 * nrows) return;
    const float* src = (gwarp < nrows) ? x : y;
    float* dst = (gwarp < nrows) ? g_nx : g_ny;
    int row = (gwarp < nrows) ? gwarp : (gwarp - nrows);
    float v0 = src[(size_t)row * CC + lane];
    float v1 = src[(size_t)row * CC + 32 + lane];
    float s = v0 * v0 + v1 * v1;
    #pragma unroll
    for (int o = 16; o; o >>= 1) s += __shfl_xor_sync(0xFFFFFFFFu, s, o);
    if (lane == 0) dst[row] = s;
}

// ---------------------------------------------------------------------------
// Kernel 1: cost[b][i][j] = x2[i] + y2[j] - 2 * dot(x_i, y_j)
// 128x128 tile per CTA, 8x8 cells per thread.
// ---------------------------------------------------------------------------
__global__ __launch_bounds__(256) void cost_kernel(const float* __restrict__ x,
                                                   const float* __restrict__ y) {
    __shared__ float xs[32][132];
    __shared__ float ys[32][132];

    int b = blockIdx.z;
    int I0 = blockIdx.y * 128;
    int J0 = blockIdx.x * 128;
    int tid = threadIdx.x;
    int tx = tid & 15;
    int ty = tid >> 4;

    const float* xb = x + ((size_t)b * TT + I0) * CC;
    const float* yb = y + ((size_t)b * TT + J0) * CC;

    float acc[8][8];
    #pragma unroll
    for (int r = 0; r < 8; r++)
        #pragma unroll
        for (int s = 0; s < 8; s++) acc[r][s] = 0.f;

    for (int k0 = 0; k0 < CC; k0 += 32) {
        __syncthreads();
        #pragma unroll
        for (int e = 0; e < 4096; e += 256) {
            int idx = e + tid;
            int row = idx >> 5;
            int kk = idx & 31;
            xs[kk][row] = xb[(size_t)row * CC + k0 + kk];
            ys[kk][row] = yb[(size_t)row * CC + k0 + kk];
        }
        __syncthreads();
        #pragma unroll
        for (int kk = 0; kk < 32; kk++) {
            float4 xv0 = *(const float4*)&xs[kk][ty * 8];
            float4 xv1 = *(const float4*)&xs[kk][ty * 8 + 4];
            float4 yv0 = *(const float4*)&ys[kk][tx * 8];
            float4 yv1 = *(const float4*)&ys[kk][tx * 8 + 4];
            float xr[8] = {xv0.x, xv0.y, xv0.z, xv0.w, xv1.x, xv1.y, xv1.z, xv1.w};
            float yr[8] = {yv0.x, yv0.y, yv0.z, yv0.w, yv1.x, yv1.y, yv1.z, yv1.w};
            #pragma unroll
            for (int r = 0; r < 8; r++)
                #pragma unroll
                for (int s = 0; s < 8; s++)
                    acc[r][s] = fmaf(xr[r], yr[s], acc[r][s]);
        }
    }

    float x2[8], y2[8];
    #pragma unroll
    for (int r = 0; r < 8; r++) x2[r] = g_nx[b * TT + I0 + ty * 8 + r];
    #pragma unroll
    for (int s = 0; s < 8; s++) y2[s] = g_ny[b * TT + J0 + tx * 8 + s];

    float* crow = g_cost + ((size_t)b << 20) + (size_t)(I0 + ty * 8) * TT + J0 + tx * 8;
    #pragma unroll
    for (int r = 0; r < 8; r++) {
        float4 o0, o1;
        o0.x = fmaf(-2.f, acc[r][0], x2[r] + y2[0]);
        o0.y = fmaf(-2.f, acc[r][1], x2[r] + y2[1]);
        o0.z = fmaf(-2.f, acc[r][2], x2[r] + y2[2]);
        o0.w = fmaf(-2.f, acc[r][3], x2[r] + y2[3]);
        o1.x = fmaf(-2.f, acc[r][4], x2[r] + y2[4]);
        o1.y = fmaf(-2.f, acc[r][5], x2[r] + y2[5]);
        o1.z = fmaf(-2.f, acc[r][6], x2[r] + y2[6]);
        o1.w = fmaf(-2.f, acc[r][7], x2[r] + y2[7]);
        *(float4*)&crow[(size_t)r * TT] = o0;
        *(float4*)&crow[(size_t)r * TT + 4] = o1;
    }
}

// ---------------------------------------------------------------------------
// Kernel 2: soft-DTW, one CTA per batch, 8 warps x (32 lanes x 4 rows).
// Lane-skewed warp pipeline: lane l computes column c = s - l at step s for
// its 4 rows (register-serial). Vertical dep lane->lane via __shfl_up;
// warp->warp via full-length smem boundary row + release/acquire flag every
// CHW columns (producers never block: no overwrite).
// Softmin fast path: when all lanes' med-min gap > 0.125, softmin == min
// exactly to ~1e-7 (gamma=0.01), so the warp skips all MUFU work.
// ---------------------------------------------------------------------------
__global__ __launch_bounds__(256) void dp_kernel() {
    const int b = blockIdx.x;
    const int tid = threadIdx.x;
    const int w = tid >> 5;
    const int lane = tid & 31;

    __shared__ float s_bnd[NW - 1][TT + 1];  // boundary rows of warps 0..6
    __shared__ int s_flag[NW];               // columns published per warp

    if (tid < NW) s_flag[tid] = 0;
    __syncthreads();

    // Lane owns rows wbase + 4*lane + 1 .. +4 (1-based).
    const int wbase = w * (32 * RPL);
    // cost base for this lane's first row (0-based row index wbase + 4*lane)
    const float* pbase = g_cost + ((size_t)b << 20) + (size_t)(wbase + RPL * lane) * TT;

    float rL0 = BIGF, rL1 = BIGF, rL2 = BIGF, rL3 = BIGF;  // R[row_k][c-1]
    float bottom = BIGF;                                    // last step's r3
    float dgTop = (w == 0 && lane == 0) ? 0.f : BIGF;       // R[rowtop-1][c-1]

    const int* flg_in = (w > 0) ? &s_flag[w - 1] : &s_flag[0];

    for (int s = 1; s <= TT + 31; ++s) {
        // lane 0 of warps 1..7 fetches the boundary value for column s
        float binv = BIGF;
        if (w > 0 && lane == 0 && s <= TT) {
            if (((s - 1) & (CHW - 1)) == 0) {
                int tgt = s + CHW - 1; if (tgt > TT) tgt = TT;
                while (ld_acq_cta(flg_in) < tgt) { }
            }
            binv = s_bnd[w - 1][s];
        }
        float upin = __shfl_up_sync(0xFFFFFFFFu, bottom, 1);
        if (lane == 0) upin = (w == 0) ? BIGF : binv;

        int c = s - lane;
        bool valid = (c >= 1) && (c <= TT);
        float nr0 = 0.f, nr1 = 0.f, nr2 = 0.f, nr3 = 0.f;
        float cv0 = 0.f, cv1 = 0.f, cv2 = 0.f, cv3 = 0.f;
        bool okall = true;

        if (valid) {
            const float* p = pbase + (c - 1);
            cv0 = p[0]; cv1 = p[TT]; cv2 = p[2 * TT]; cv3 = p[3 * TT];

            // fast chain: softmin == min when med - min > GAP_THRESH
            float up = upin, dg = dgTop;
            bool ok;
            {
                float a = rL0;
                float lo = fminf(a, up), hi = fmaxf(a, up);
                float m = fminf(lo, dg);
                float med = fminf(hi, fmaxf(lo, dg));
                ok = (med - m) > GAP_THRESH;
                nr0 = cv0 + m; dg = a; up = nr0;
            }
            {
                float a = rL1;
                float lo = fminf(a, up), hi = fmaxf(a, up);
                float m = fminf(lo, dg);
                float med = fminf(hi, fmaxf(lo, dg));
                ok = ok && ((med - m) > GAP_THRESH);
                nr1 = cv1 + m; dg = a; up = nr1;
            }
            {
                float a = rL2;
                float lo = fminf(a, up), hi = fmaxf(a, up);
                float m = fminf(lo, dg);
                float med = fminf(hi, fmaxf(lo, dg));
                ok = ok && ((med - m) > GAP_THRESH);
                nr2 = cv2 + m; dg = a; up = nr2;
            }
            {
                float a = rL3;
                float lo = fminf(a, up), hi = fmaxf(a, up);
                float m = fminf(lo, dg);
                float med = fminf(hi, fmaxf(lo, dg));
                ok = ok && ((med - m) > GAP_THRESH);
                nr3 = cv3 + m; dg = a; up = nr3;
            }
            okall = ok;
        }

        if (!__all_sync(0xFFFFFFFFu, okall)) {
            // exact redo (rare): full softmin chain from the original inputs
            if (valid) {
                float up = upin, dg = dgTop;
                {
                    float a = rL0;
                    float lo = fminf(a, up), hi = fmaxf(a, up);
                    float m = fminf(lo, dg);
                    float med = fminf(hi, fmaxf(lo, dg));
                    float q = fmaxf(hi, dg);
                    float e = 1.f + ex2f((m - med) * KS) + ex2f((m - q) * KS);
                    nr0 = cv0 + m - GLN2 * lg2f(e);
                    dg = a; up = nr0;
                }
                {
                    float a = rL1;
                    float lo = fminf(a, up), hi = fmaxf(a, up);
                    float m = fminf(lo, dg);
                    float med = fminf(hi, fmaxf(lo, dg));
                    float q = fmaxf(hi, dg);
                    float e = 1.f + ex2f((m - med) * KS) + ex2f((m - q) * KS);
                    nr1 = cv1 + m - GLN2 * lg2f(e);
                    dg = a; up = nr1;
                }
                {
                    float a = rL2;
                    float lo = fminf(a, up), hi = fmaxf(a, up);
                    float m = fminf(lo, dg);
                    float med = fminf(hi, fmaxf(lo, dg));
                    float q = fmaxf(hi, dg);
                    float e = 1.f + ex2f((m - med) * KS) + ex2f((m - q) * KS);
                    nr2 = cv2 + m - GLN2 * lg2f(e);
                    dg = a; up = nr2;
                }
                {
                    float a = rL3;
                    float lo = fminf(a, up), hi = fmaxf(a, up);
                    float m = fminf(lo, dg);
                    float med = fminf(hi, fmaxf(lo, dg));
                    float q = fmaxf(hi, dg);
                    float e = 1.f + ex2f((m - med) * KS) + ex2f((m - q) * KS);
                    nr3 = cv3 + m - GLN2 * lg2f(e);
                    dg = a; up = nr3;
                }
            }
        }

        if (valid) {
            rL0 = nr0; rL1 = nr1; rL2 = nr2; rL3 = nr3;
            bottom = nr3;
            dgTop = upin;
            if (lane == 31) {
                if (w < NW - 1) {
                    s_bnd[w][c] = nr3;
                    if ((c & (CHW - 1)) == 0) st_rel_cta(&s_flag[w], c);
                } else if (c == TT) {
                    g_partial[b] = nr3;   // R[T][T]
                }
            }
        }
    }
}

// ---------------------------------------------------------------------------
// Kernel 3: deterministic sum of the 16 per-batch distances.
// ---------------------------------------------------------------------------
__global__ void sum_kernel(float* out) {
    if (threadIdx.x == 0) {
        float s = 0.f;
        #pragma unroll
        for (int b = 0; b < BB; b++) s += g_partial[b];
        out[0] = s;
    }
}

extern "C" void kernel_launch(void* const* d_in, const int* in_sizes, int n_in,
                              void* d_out, int out_size) {
    const float* x = (const float*)d_in[0];
    const float* y = (const float*)d_in[1];
    float* out = (float*)d_out;

    norms_kernel<<<4096, 256>>>(x, y);
    cost_kernel<<<dim3(8, 8, BB), 256>>>(x, y);
    dp_kernel<<<BB, 256>>>();
    sum_kernel<<<1, 32>>>(out);
}

// round 5
// speedup vs baseline: 1.6407x; 1.6407x over previous
#include <cuda_runtime.h>
#include <cstddef>

#define TT 1024
#define BB 16
#define CC 64
#define BIGF 1e10f
// 1/(gamma*ln2), gamma = 0.01
#define KS 144.2695040888963f
// gamma*ln2
#define GLN2 0.006931471805599453f

// Scratch (device globals: allocation-free rule)
// Anti-diagonal-major cost: entry (i,j) 1-based lives at [b][(i+j)-2][i-1].
__device__ float g_costd[(size_t)BB * 2047 * 1024];   // 134 MB
__device__ float g_nx[BB * TT];
__device__ float g_ny[BB * TT];
__device__ float g_partial[BB];

__device__ __forceinline__ float ex2f(float x) {
    float y;
    asm("ex2.approx.ftz.f32 %0, %1;" : "=f"(y) : "f"(x));
    return y;
}
__device__ __forceinline__ float lg2f(float x) {
    float y;
    asm("lg2.approx.ftz.f32 %0, %1;" : "=f"(y) : "f"(x));
    return y;
}

// ---------------------------------------------------------------------------
// Kernel 0: row norms  ||x_i||^2, ||y_j||^2  (one warp per row)
// ---------------------------------------------------------------------------
__global__ void norms_kernel(const float* __restrict__ x,
                             const float* __restrict__ y) {
    int gwarp = (blockIdx.x * blockDim.x + threadIdx.x) >> 5;
    int lane = threadIdx.x & 31;
    const int nrows = BB * TT;
    if (gwarp >= 2 * nrows) return;
    const float* src = (gwarp < nrows) ? x : y;
    float* dst = (gwarp < nrows) ? g_nx : g_ny;
    int row = (gwarp < nrows) ? gwarp : (gwarp - nrows);
    float v0 = src[(size_t)row * CC + lane];
    float v1 = src[(size_t)row * CC + 32 + lane];
    float s = v0 * v0 + v1 * v1;
    #pragma unroll
    for (int o = 16; o; o >>= 1) s += __shfl_xor_sync(0xFFFFFFFFu, s, o);
    if (lane == 0) dst[row] = s;
}

// ---------------------------------------------------------------------------
// Kernel 1: cost tile 128x128 per CTA (8x8 regs/thread), then scatter the
// tile to anti-diagonal-major g_costd via smem (2 phases of 64 rows).
// smem tile pitch 132: anti-diagonal read stride 131 (odd) -> conflict-free,
// and 132 keeps float4 stores 16B-aligned.
// ---------------------------------------------------------------------------
#define PITCH 132
__global__ __launch_bounds__(256) void cost_kernel(const float* __restrict__ x,
                                                   const float* __restrict__ y) {
    __shared__ float sbuf[8448];   // union: xs[32*132] + ys[32*132] | tile 64*132
    float* xs = sbuf;              // [kk][row] -> kk*132 + row
    float* ys = sbuf + 4224;

    int b = blockIdx.z;
    int I0 = blockIdx.y * 128;
    int J0 = blockIdx.x * 128;
    int tid = threadIdx.x;
    int tx = tid & 15;
    int ty = tid >> 4;
    int w = tid >> 5;
    int lane = tid & 31;

    const float* xb = x + ((size_t)b * TT + I0) * CC;
    const float* yb = y + ((size_t)b * TT + J0) * CC;

    float acc[8][8];
    #pragma unroll
    for (int r = 0; r < 8; r++)
        #pragma unroll
        for (int s = 0; s < 8; s++) acc[r][s] = 0.f;

    for (int k0 = 0; k0 < CC; k0 += 32) {
        __syncthreads();
        #pragma unroll
        for (int e = 0; e < 4096; e += 256) {
            int idx = e + tid;
            int row = idx >> 5;
            int kk = idx & 31;
            xs[kk * 132 + row] = xb[(size_t)row * CC + k0 + kk];
            ys[kk * 132 + row] = yb[(size_t)row * CC + k0 + kk];
        }
        __syncthreads();
        #pragma unroll
        for (int kk = 0; kk < 32; kk++) {
            float4 xv0 = *(const float4*)&xs[kk * 132 + ty * 8];
            float4 xv1 = *(const float4*)&xs[kk * 132 + ty * 8 + 4];
            float4 yv0 = *(const float4*)&ys[kk * 132 + tx * 8];
            float4 yv1 = *(const float4*)&ys[kk * 132 + tx * 8 + 4];
            float xr[8] = {xv0.x, xv0.y, xv0.z, xv0.w, xv1.x, xv1.y, xv1.z, xv1.w};
            float yr[8] = {yv0.x, yv0.y, yv0.z, yv0.w, yv1.x, yv1.y, yv1.z, yv1.w};
            #pragma unroll
            for (int r = 0; r < 8; r++)
                #pragma unroll
                for (int s = 0; s < 8; s++)
                    acc[r][s] = fmaf(xr[r], yr[s], acc[r][s]);
        }
    }

    float x2[8], y2[8];
    #pragma unroll
    for (int r = 0; r < 8; r++) x2[r] = g_nx[b * TT + I0 + ty * 8 + r];
    #pragma unroll
    for (int s = 0; s < 8; s++) y2[s] = g_ny[b * TT + J0 + tx * 8 + s];

    float* slab = g_costd + (size_t)b * 2047 * 1024;

    #pragma unroll
    for (int ph = 0; ph < 2; ph++) {
        __syncthreads();   // previous phase reads done / xs,ys done
        if ((ty >> 3) == ph) {
            int rl = (ty & 7) * 8;   // local row base in this phase
            #pragma unroll
            for (int r = 0; r < 8; r++) {
                float4 o0, o1;
                o0.x = fmaf(-2.f, acc[r][0], x2[r] + y2[0]);
                o0.y = fmaf(-2.f, acc[r][1], x2[r] + y2[1]);
                o0.z = fmaf(-2.f, acc[r][2], x2[r] + y2[2]);
                o0.w = fmaf(-2.f, acc[r][3], x2[r] + y2[3]);
                o1.x = fmaf(-2.f, acc[r][4], x2[r] + y2[4]);
                o1.y = fmaf(-2.f, acc[r][5], x2[r] + y2[5]);
                o1.z = fmaf(-2.f, acc[r][6], x2[r] + y2[6]);
                o1.w = fmaf(-2.f, acc[r][7], x2[r] + y2[7]);
                *(float4*)&sbuf[(rl + r) * PITCH + tx * 8] = o0;
                *(float4*)&sbuf[(rl + r) * PITCH + tx * 8 + 4] = o1;
            }
        }
        __syncthreads();
        // scatter: global rows r in [ph*64, ph*64+63], D = r + c
        int Dlo = ph * 64, Dhi = ph * 64 + 190;
        for (int D = Dlo + w; D <= Dhi; D += 8) {
            int rlo = ph * 64;      if (D - 127 > rlo) rlo = D - 127;
            int rhi = ph * 64 + 63; if (D < rhi) rhi = D;
            int len = rhi - rlo + 1;
            if (len <= 0) continue;
            float* gout = slab + (size_t)(I0 + J0 + D) * 1024 + I0 + rlo;
            int sb = (rlo - ph * 64) * PITCH + (D - rlo);
            for (int k = lane; k < len; k += 32)
                gout[k] = sbuf[sb + k * (PITCH - 1)];
        }
    }
}

// ---------------------------------------------------------------------------
// Kernel 2: soft-DTW wavefront, one CTA per batch, 256 threads, 4 rows/thread.
// rp[k] = R[row_k][.] on diagonal d-1, qp[k] on d-2 (registers).
// Neighbor values via shfl_up; warp boundary via 3-slot rotating smem edge.
// Coalesced float4 cost loads from diag-major slab, depth-2 prefetch.
// Softmin: exps underflow (2^-16) when (med-min)*KS > 16 -> skip MUFU.
// ---------------------------------------------------------------------------
__global__ __launch_bounds__(256) void dp_kernel() {
    const int b = blockIdx.x;
    const int tid = threadIdx.x;
    const int w = tid >> 5;
    const int lane = tid & 31;

    __shared__ float s_edge[3][8];
    if (tid < 24) ((float*)s_edge)[tid] = BIGF;
    __syncthreads();

    const int I = 4 * tid + 1;                    // first row (1-based)
    const float* base = g_costd + (size_t)b * 2047 * 1024 + 4 * tid;

    float rp0 = BIGF, rp1 = BIGF, rp2 = BIGF, rp3 = BIGF;
    float qp0 = BIGF, qp1 = BIGF, qp2 = BIGF, qp3 = BIGF;

    const int wlo = 128 * w + 2;
    const int whi = 128 * w + 128 + TT;

    float4 cva = *(const float4*)(base);          // d=2
    float4 cvb = *(const float4*)(base + 1024);   // d=3
    float4 cvn = cva;
    int i0 = 2, i1 = 1, i2 = 0;                   // d%3, (d-1)%3, (d-2)%3

    for (int d = 2; d <= 2 * TT; ++d) {
        if (d + 2 <= 2 * TT)
            cvn = *(const float4*)(base + (size_t)d * 1024);   // slab row d = (d+2)-2

        bool act = (d >= wlo) && (d <= whi);
        if (act) {
            float u_sh = __shfl_up_sync(0xFFFFFFFFu, rp3, 1);
            float g_sh = __shfl_up_sync(0xFFFFFFFFu, qp3, 1);
            if (lane == 0) {
                if (w == 0) { u_sh = BIGF; g_sh = (d == 2) ? 0.f : BIGF; }
                else { u_sh = s_edge[i1][w - 1]; g_sh = s_edge[i2][w - 1]; }
            }
            int jm1 = d - I - 1;   // j-1 for cell 0
            float nr0, nr1, nr2, nr3;
            {   // cell 0: a=rp0 u=u_sh g=g_sh
                float lo = fminf(rp0, u_sh), hi = fmaxf(rp0, u_sh);
                float m = fminf(lo, g_sh);
                float med = fminf(hi, fmaxf(lo, g_sh));
                bool v = (unsigned)jm1 < 1024u;
                float gk = (m - med) * KS;
                float r = cva.x + m;
                if (v && gk > -16.f) {
                    float mx = fmaxf(hi, g_sh);
                    float e = 1.f + ex2f(gk) + ex2f((m - mx) * KS);
                    r = cva.x + m - GLN2 * lg2f(e);
                }
                nr0 = v ? r : BIGF;
            }
            {   // cell 1: a=rp1 u=rp0 g=qp0
                float lo = fminf(rp1, rp0), hi = fmaxf(rp1, rp0);
                float m = fminf(lo, qp0);
                float med = fminf(hi, fmaxf(lo, qp0));
                bool v = (unsigned)(jm1 - 1) < 1024u;
                float gk = (m - med) * KS;
                float r = cva.y + m;
                if (v && gk > -16.f) {
                    float mx = fmaxf(hi, qp0);
                    float e = 1.f + ex2f(gk) + ex2f((m - mx) * KS);
                    r = cva.y + m - GLN2 * lg2f(e);
                }
                nr1 = v ? r : BIGF;
            }
            {   // cell 2: a=rp2 u=rp1 g=qp1
                float lo = fminf(rp2, rp1), hi = fmaxf(rp2, rp1);
                float m = fminf(lo, qp1);
                float med = fminf(hi, fmaxf(lo, qp1));
                bool v = (unsigned)(jm1 - 2) < 1024u;
                float gk = (m - med) * KS;
                float r = cva.z + m;
                if (v && gk > -16.f) {
                    float mx = fmaxf(hi, qp1);
                    float e = 1.f + ex2f(gk) + ex2f((m - mx) * KS);
                    r = cva.z + m - GLN2 * lg2f(e);
                }
                nr2 = v ? r : BIGF;
            }
            {   // cell 3: a=rp3 u=rp2 g=qp2
                float lo = fminf(rp3, rp2), hi = fmaxf(rp3, rp2);
                float m = fminf(lo, qp2);
                float med = fminf(hi, fmaxf(lo, qp2));
                bool v = (unsigned)(jm1 - 3) < 1024u;
                float gk = (m - med) * KS;
                float r = cva.w + m;
                if (v && gk > -16.f) {
                    float mx = fmaxf(hi, qp2);
                    float e = 1.f + ex2f(gk) + ex2f((m - mx) * KS);
                    r = cva.w + m - GLN2 * lg2f(e);
                }
                nr3 = v ? r : BIGF;
            }
            qp0 = rp0; qp1 = rp1; qp2 = rp2; qp3 = rp3;
            rp0 = nr0; rp1 = nr1; rp2 = nr2; rp3 = nr3;
        }
        if (lane == 31) s_edge[i0][w] = rp3;
        __syncthreads();
        int t = i2; i2 = i1; i1 = i0; i0 = t;
        cva = cvb; cvb = cvn;
    }

    if (tid == 255) g_partial[b] = rp3;   // R[T][T]
}

// ---------------------------------------------------------------------------
// Kernel 3: deterministic sum of the 16 per-batch distances.
// ---------------------------------------------------------------------------
__global__ void sum_kernel(float* out) {
    if (threadIdx.x == 0) {
        float s = 0.f;
        #pragma unroll
        for (int b = 0; b < BB; b++) s += g_partial[b];
        out[0] = s;
    }
}

extern "C" void kernel_launch(void* const* d_in, const int* in_sizes, int n_in,
                              void* d_out, int out_size) {
    const float* x = (const float*)d_in[0];
    const float* y = (const float*)d_in[1];
    float* out = (float*)d_out;

    norms_kernel<<<4096, 256>>>(x, y);
    cost_kernel<<<dim3(8, 8, BB), 256>>>(x, y);
    dp_kernel<<<BB, 256>>>();
    sum_kernel<<<1, 32>>>(out);
}

// round 6
// speedup vs baseline: 2.6545x; 1.6179x over previous
#include <cuda_runtime.h>
#include <cstddef>

#define TT 1024
#define BB 16
#define CC 64
#define BIGF 1e10f
// 1/(gamma*ln2), gamma = 0.01
#define KS 144.2695040888963f
// gamma*ln2
#define GLN2 0.006931471805599453f

// Scratch (device globals: allocation-free rule)
// Anti-diagonal-major cost: entry (i,j) 1-based lives at [b][(i+j)-2][i-1].
__device__ float g_costd[(size_t)BB * 2047 * 1024];   // 134 MB
__device__ float g_nx[BB * TT];
__device__ float g_ny[BB * TT];
__device__ float g_partial[BB];

__device__ __forceinline__ float ex2f(float x) {
    float y;
    asm("ex2.approx.ftz.f32 %0, %1;" : "=f"(y) : "f"(x));
    return y;
}
__device__ __forceinline__ float lg2f(float x) {
    float y;
    asm("lg2.approx.ftz.f32 %0, %1;" : "=f"(y) : "f"(x));
    return y;
}

// ---------------------------------------------------------------------------
// Kernel 0: row norms  ||x_i||^2, ||y_j||^2  (one warp per row)
// ---------------------------------------------------------------------------
__global__ void norms_kernel(const float* __restrict__ x,
                             const float* __restrict__ y) {
    int gwarp = (blockIdx.x * blockDim.x + threadIdx.x) >> 5;
    int lane = threadIdx.x & 31;
    const int nrows = BB * TT;
    if (gwarp >= 2 * nrows) return;
    const float* src = (gwarp < nrows) ? x : y;
    float* dst = (gwarp < nrows) ? g_nx : g_ny;
    int row = (gwarp < nrows) ? gwarp : (gwarp - nrows);
    float v0 = src[(size_t)row * CC + lane];
    float v1 = src[(size_t)row * CC + 32 + lane];
    float s = v0 * v0 + v1 * v1;
    #pragma unroll
    for (int o = 16; o; o >>= 1) s += __shfl_xor_sync(0xFFFFFFFFu, s, o);
    if (lane == 0) dst[row] = s;
}

// ---------------------------------------------------------------------------
// Kernel 1: cost tile 128x128 per CTA (8x8 regs/thread), then scatter the
// tile to anti-diagonal-major g_costd via smem (2 phases of 64 rows).
// ---------------------------------------------------------------------------
#define PITCH 132
__global__ __launch_bounds__(256) void cost_kernel(const float* __restrict__ x,
                                                   const float* __restrict__ y) {
    __shared__ float sbuf[8448];   // union: xs[32*132] + ys[32*132] | tile 64*132
    float* xs = sbuf;              // [kk][row] -> kk*132 + row
    float* ys = sbuf + 4224;

    int b = blockIdx.z;
    int I0 = blockIdx.y * 128;
    int J0 = blockIdx.x * 128;
    int tid = threadIdx.x;
    int tx = tid & 15;
    int ty = tid >> 4;
    int w = tid >> 5;
    int lane = tid & 31;

    const float* xb = x + ((size_t)b * TT + I0) * CC;
    const float* yb = y + ((size_t)b * TT + J0) * CC;

    float acc[8][8];
    #pragma unroll
    for (int r = 0; r < 8; r++)
        #pragma unroll
        for (int s = 0; s < 8; s++) acc[r][s] = 0.f;

    for (int k0 = 0; k0 < CC; k0 += 32) {
        __syncthreads();
        #pragma unroll
        for (int e = 0; e < 4096; e += 256) {
            int idx = e + tid;
            int row = idx >> 5;
            int kk = idx & 31;
            xs[kk * 132 + row] = xb[(size_t)row * CC + k0 + kk];
            ys[kk * 132 + row] = yb[(size_t)row * CC + k0 + kk];
        }
        __syncthreads();
        #pragma unroll
        for (int kk = 0; kk < 32; kk++) {
            float4 xv0 = *(const float4*)&xs[kk * 132 + ty * 8];
            float4 xv1 = *(const float4*)&xs[kk * 132 + ty * 8 + 4];
            float4 yv0 = *(const float4*)&ys[kk * 132 + tx * 8];
            float4 yv1 = *(const float4*)&ys[kk * 132 + tx * 8 + 4];
            float xr[8] = {xv0.x, xv0.y, xv0.z, xv0.w, xv1.x, xv1.y, xv1.z, xv1.w};
            float yr[8] = {yv0.x, yv0.y, yv0.z, yv0.w, yv1.x, yv1.y, yv1.z, yv1.w};
            #pragma unroll
            for (int r = 0; r < 8; r++)
                #pragma unroll
                for (int s = 0; s < 8; s++)
                    acc[r][s] = fmaf(xr[r], yr[s], acc[r][s]);
        }
    }

    float x2[8], y2[8];
    #pragma unroll
    for (int r = 0; r < 8; r++) x2[r] = g_nx[b * TT + I0 + ty * 8 + r];
    #pragma unroll
    for (int s = 0; s < 8; s++) y2[s] = g_ny[b * TT + J0 + tx * 8 + s];

    float* slab = g_costd + (size_t)b * 2047 * 1024;

    #pragma unroll
    for (int ph = 0; ph < 2; ph++) {
        __syncthreads();
        if ((ty >> 3) == ph) {
            int rl = (ty & 7) * 8;
            #pragma unroll
            for (int r = 0; r < 8; r++) {
                float4 o0, o1;
                o0.x = fmaf(-2.f, acc[r][0], x2[r] + y2[0]);
                o0.y = fmaf(-2.f, acc[r][1], x2[r] + y2[1]);
                o0.z = fmaf(-2.f, acc[r][2], x2[r] + y2[2]);
                o0.w = fmaf(-2.f, acc[r][3], x2[r] + y2[3]);
                o1.x = fmaf(-2.f, acc[r][4], x2[r] + y2[4]);
                o1.y = fmaf(-2.f, acc[r][5], x2[r] + y2[5]);
                o1.z = fmaf(-2.f, acc[r][6], x2[r] + y2[6]);
                o1.w = fmaf(-2.f, acc[r][7], x2[r] + y2[7]);
                *(float4*)&sbuf[(rl + r) * PITCH + tx * 8] = o0;
                *(float4*)&sbuf[(rl + r) * PITCH + tx * 8 + 4] = o1;
            }
        }
        __syncthreads();
        int Dlo = ph * 64, Dhi = ph * 64 + 190;
        for (int D = Dlo + w; D <= Dhi; D += 8) {
            int rlo = ph * 64;      if (D - 127 > rlo) rlo = D - 127;
            int rhi = ph * 64 + 63; if (D < rhi) rhi = D;
            int len = rhi - rlo + 1;
            if (len <= 0) continue;
            float* gout = slab + (size_t)(I0 + J0 + D) * 1024 + I0 + rlo;
            int sb = (rlo - ph * 64) * PITCH + (D - rlo);
            for (int k = lane; k < len; k += 32)
                gout[k] = sbuf[sb + k * (PITCH - 1)];
        }
    }
}

// ---------------------------------------------------------------------------
// Kernel 2: soft-DTW wavefront, one CTA per batch, 256 threads, 4 rows/thread.
// Deep register prefetch: diagonal loop unrolled x4 with triple-buffered
// float4 queues (cur/nxt/nn) -> 4 independent loads in flight targeted 8-11
// diagonals ahead; DRAM latency fully hidden.
// ---------------------------------------------------------------------------
__device__ __forceinline__ void cellf(float a, float up, float dg, float cv,
                                      bool v, float& out) {
    float lo = fminf(a, up), hi = fmaxf(a, up);
    float m = fminf(lo, dg);
    float med = fminf(hi, fmaxf(lo, dg));
    float gk = (m - med) * KS;
    float r = cv + m;
    if (v && gk > -16.f) {
        float mx = fmaxf(hi, dg);
        float e = 1.f + ex2f(gk) + ex2f((m - mx) * KS);
        r = cv + m - GLN2 * lg2f(e);
    }
    out = v ? r : BIGF;
}

__device__ __forceinline__ void step_diag(
    int d, int w, int lane, int I, int wlo, int whi, float4 cva,
    float& rp0, float& rp1, float& rp2, float& rp3,
    float& qp0, float& qp1, float& qp2, float& qp3,
    float s_edge[3][8], int i0, int i1, int i2)
{
    bool act = (d >= wlo) && (d <= whi);
    if (act) {
        float u_sh = __shfl_up_sync(0xFFFFFFFFu, rp3, 1);
        float g_sh = __shfl_up_sync(0xFFFFFFFFu, qp3, 1);
        if (lane == 0) {
            if (w == 0) { u_sh = BIGF; g_sh = (d == 2) ? 0.f : BIGF; }
            else { u_sh = s_edge[i1][w - 1]; g_sh = s_edge[i2][w - 1]; }
        }
        int jm1 = d - I - 1;
        float nr0, nr1, nr2, nr3;
        cellf(rp0, u_sh, g_sh, cva.x, (unsigned)jm1 < 1024u, nr0);
        cellf(rp1, rp0, qp0, cva.y, (unsigned)(jm1 - 1) < 1024u, nr1);
        cellf(rp2, rp1, qp1, cva.z, (unsigned)(jm1 - 2) < 1024u, nr2);
        cellf(rp3, rp2, qp2, cva.w, (unsigned)(jm1 - 3) < 1024u, nr3);
        qp0 = rp0; qp1 = rp1; qp2 = rp2; qp3 = rp3;
        rp0 = nr0; rp1 = nr1; rp2 = nr2; rp3 = nr3;
    }
    if (lane == 31) s_edge[i0][w] = rp3;
    __syncthreads();
}

__global__ __launch_bounds__(256) void dp_kernel() {
    const int b = blockIdx.x;
    const int tid = threadIdx.x;
    const int w = tid >> 5;
    const int lane = tid & 31;

    __shared__ float s_edge[3][8];
    if (tid < 24) ((float*)s_edge)[tid] = BIGF;
    __syncthreads();

    const int I = 4 * tid + 1;                    // first row (1-based)
    const float* base = g_costd + (size_t)b * 2047 * 1024 + 4 * tid;
    // slab row for diagonal d is (d-2); rows valid 0..2046

    float rp0 = BIGF, rp1 = BIGF, rp2 = BIGF, rp3 = BIGF;
    float qp0 = BIGF, qp1 = BIGF, qp2 = BIGF, qp3 = BIGF;

    const int wlo = 128 * w + 2;
    const int whi = 128 * w + 128 + TT;

    float4 cur[4], nxt[4];
    #pragma unroll
    for (int k = 0; k < 4; k++)
        cur[k] = *(const float4*)(base + (size_t)k * 1024);          // diags 2..5
    #pragma unroll
    for (int k = 0; k < 4; k++)
        nxt[k] = *(const float4*)(base + (size_t)(4 + k) * 1024);    // diags 6..9

    int i0 = 2, i1 = 1, i2 = 0;

    for (int d0 = 2; d0 <= 2046; d0 += 4) {
        // prefetch diagonals d0+8 .. d0+11 (rows d0+6 .. d0+9, clamped)
        float4 nn[4];
        #pragma unroll
        for (int k = 0; k < 4; k++) {
            int ri = d0 + 6 + k;
            if (ri > 2046) ri = 2046;
            nn[k] = *(const float4*)(base + (size_t)ri * 1024);
        }

        #pragma unroll
        for (int k = 0; k < 4; k++) {
            int d = d0 + k;
            if (d <= 2048) {
                step_diag(d, w, lane, I, wlo, whi, cur[k],
                          rp0, rp1, rp2, rp3, qp0, qp1, qp2, qp3,
                          s_edge, i0, i1, i2);
                int t = i2; i2 = i1; i1 = i0; i0 = t;
            }
        }

        #pragma unroll
        for (int k = 0; k < 4; k++) { cur[k] = nxt[k]; nxt[k] = nn[k]; }
    }

    if (tid == 255) g_partial[b] = rp3;   // R[T][T]
}

// ---------------------------------------------------------------------------
// Kernel 3: deterministic sum of the 16 per-batch distances.
// ---------------------------------------------------------------------------
__global__ void sum_kernel(float* out) {
    if (threadIdx.x == 0) {
        float s = 0.f;
        #pragma unroll
        for (int b = 0; b < BB; b++) s += g_partial[b];
        out[0] = s;
    }
}

extern "C" void kernel_launch(void* const* d_in, const int* in_sizes, int n_in,
                              void* d_out, int out_size) {
    const float* x = (const float*)d_in[0];
    const float* y = (const float*)d_in[1];
    float* out = (float*)d_out;

    norms_kernel<<<4096, 256>>>(x, y);
    cost_kernel<<<dim3(8, 8, BB), 256>>>(x, y);
    dp_kernel<<<BB, 256>>>();
    sum_kernel<<<1, 32>>>(out);
}

// round 7
// speedup vs baseline: 3.1999x; 1.2055x over previous
#include <cuda_runtime.h>
#include <cstddef>

#define TT 1024
#define BB 16
#define CC 64
#define BIGF 1e10f
// 1/(gamma*ln2), gamma = 0.01
#define KS 144.2695040888963f
// gamma*ln2
#define GLN2 0.006931471805599453f
// (med - min) threshold below which exp terms matter (16 / KS)
#define GAPT 0.11090354888959125f

// Scratch (device globals: allocation-free rule)
// Anti-diagonal-major cost: entry (i,j) 1-based lives at [b][(i+j)-2][i-1].
__device__ float g_costd[(size_t)BB * 2047 * 1024];   // 134 MB
__device__ float g_nx[BB * TT];
__device__ float g_ny[BB * TT];
__device__ float g_partial[BB];

__device__ __forceinline__ float ex2f(float x) {
    float y;
    asm("ex2.approx.ftz.f32 %0, %1;" : "=f"(y) : "f"(x));
    return y;
}
__device__ __forceinline__ float lg2f(float x) {
    float y;
    asm("lg2.approx.ftz.f32 %0, %1;" : "=f"(y) : "f"(x));
    return y;
}

// ---------------------------------------------------------------------------
// Kernel 0: row norms  ||x_i||^2, ||y_j||^2  (one warp per row)
// ---------------------------------------------------------------------------
__global__ void norms_kernel(const float* __restrict__ x,
                             const float* __restrict__ y) {
    int gwarp = (blockIdx.x * blockDim.x + threadIdx.x) >> 5;
    int lane = threadIdx.x & 31;
    const int nrows = BB * TT;
    if (gwarp >= 2 * nrows) return;
    const float* src = (gwarp < nrows) ? x : y;
    float* dst = (gwarp < nrows) ? g_nx : g_ny;
    int row = (gwarp < nrows) ? gwarp : (gwarp - nrows);
    float v0 = src[(size_t)row * CC + lane];
    float v1 = src[(size_t)row * CC + 32 + lane];
    float s = v0 * v0 + v1 * v1;
    #pragma unroll
    for (int o = 16; o; o >>= 1) s += __shfl_xor_sync(0xFFFFFFFFu, s, o);
    if (lane == 0) dst[row] = s;
}

// ---------------------------------------------------------------------------
// Kernel 1: cost tile 128x128 per CTA (8x8 regs/thread), then scatter the
// tile to anti-diagonal-major g_costd via smem (2 phases of 64 rows).
// ---------------------------------------------------------------------------
#define PITCH 132
__global__ __launch_bounds__(256) void cost_kernel(const float* __restrict__ x,
                                                   const float* __restrict__ y) {
    __shared__ float sbuf[8448];   // union: xs[32*132] + ys[32*132] | tile 64*132
    float* xs = sbuf;              // [kk][row] -> kk*132 + row
    float* ys = sbuf + 4224;

    int b = blockIdx.z;
    int I0 = blockIdx.y * 128;
    int J0 = blockIdx.x * 128;
    int tid = threadIdx.x;
    int tx = tid & 15;
    int ty = tid >> 4;
    int w = tid >> 5;
    int lane = tid & 31;

    const float* xb = x + ((size_t)b * TT + I0) * CC;
    const float* yb = y + ((size_t)b * TT + J0) * CC;

    float acc[8][8];
    #pragma unroll
    for (int r = 0; r < 8; r++)
        #pragma unroll
        for (int s = 0; s < 8; s++) acc[r][s] = 0.f;

    for (int k0 = 0; k0 < CC; k0 += 32) {
        __syncthreads();
        #pragma unroll
        for (int e = 0; e < 4096; e += 256) {
            int idx = e + tid;
            int row = idx >> 5;
            int kk = idx & 31;
            xs[kk * 132 + row] = xb[(size_t)row * CC + k0 + kk];
            ys[kk * 132 + row] = yb[(size_t)row * CC + k0 + kk];
        }
        __syncthreads();
        #pragma unroll
        for (int kk = 0; kk < 32; kk++) {
            float4 xv0 = *(const float4*)&xs[kk * 132 + ty * 8];
            float4 xv1 = *(const float4*)&xs[kk * 132 + ty * 8 + 4];
            float4 yv0 = *(const float4*)&ys[kk * 132 + tx * 8];
            float4 yv1 = *(const float4*)&ys[kk * 132 + tx * 8 + 4];
            float xr[8] = {xv0.x, xv0.y, xv0.z, xv0.w, xv1.x, xv1.y, xv1.z, xv1.w};
            float yr[8] = {yv0.x, yv0.y, yv0.z, yv0.w, yv1.x, yv1.y, yv1.z, yv1.w};
            #pragma unroll
            for (int r = 0; r < 8; r++)
                #pragma unroll
                for (int s = 0; s < 8; s++)
                    acc[r][s] = fmaf(xr[r], yr[s], acc[r][s]);
        }
    }

    float x2[8], y2[8];
    #pragma unroll
    for (int r = 0; r < 8; r++) x2[r] = g_nx[b * TT + I0 + ty * 8 + r];
    #pragma unroll
    for (int s = 0; s < 8; s++) y2[s] = g_ny[b * TT + J0 + tx * 8 + s];

    float* slab = g_costd + (size_t)b * 2047 * 1024;

    #pragma unroll
    for (int ph = 0; ph < 2; ph++) {
        __syncthreads();
        if ((ty >> 3) == ph) {
            int rl = (ty & 7) * 8;
            #pragma unroll
            for (int r = 0; r < 8; r++) {
                float4 o0, o1;
                o0.x = fmaf(-2.f, acc[r][0], x2[r] + y2[0]);
                o0.y = fmaf(-2.f, acc[r][1], x2[r] + y2[1]);
                o0.z = fmaf(-2.f, acc[r][2], x2[r] + y2[2]);
                o0.w = fmaf(-2.f, acc[r][3], x2[r] + y2[3]);
                o1.x = fmaf(-2.f, acc[r][4], x2[r] + y2[4]);
                o1.y = fmaf(-2.f, acc[r][5], x2[r] + y2[5]);
                o1.z = fmaf(-2.f, acc[r][6], x2[r] + y2[6]);
                o1.w = fmaf(-2.f, acc[r][7], x2[r] + y2[7]);
                *(float4*)&sbuf[(rl + r) * PITCH + tx * 8] = o0;
                *(float4*)&sbuf[(rl + r) * PITCH + tx * 8 + 4] = o1;
            }
        }
        __syncthreads();
        int Dlo = ph * 64, Dhi = ph * 64 + 190;
        for (int D = Dlo + w; D <= Dhi; D += 8) {
            int rlo = ph * 64;      if (D - 127 > rlo) rlo = D - 127;
            int rhi = ph * 64 + 63; if (D < rhi) rhi = D;
            int len = rhi - rlo + 1;
            if (len <= 0) continue;
            float* gout = slab + (size_t)(I0 + J0 + D) * 1024 + I0 + rlo;
            int sb = (rlo - ph * 64) * PITCH + (D - rlo);
            for (int k = lane; k < len; k += 32)
                gout[k] = sbuf[sb + k * (PITCH - 1)];
        }
    }
}

// ---------------------------------------------------------------------------
// Kernel 2: soft-DTW wavefront, one CTA per batch, 256 threads, 4 rows/thread.
// - deep register prefetch (x4 unroll, triple-buffered float4 queues)
// - ONE shfl + ONE edge LDS per diagonal (g_sh carried: g_sh(d) = u_sh(d-1))
// - branchless fast path (5 FMNMX/cell), one warp-uniform __any_sync vote
//   guarding a single exact MUFU slow-path block (rare)
// ---------------------------------------------------------------------------
__device__ __forceinline__ void cell_fast(float a, float up, float dg, float cv,
                                          bool v, float& nr, bool& need) {
    float lo = fminf(a, up), hi = fmaxf(a, up);
    float m = fminf(lo, dg);
    float med = fminf(hi, fmaxf(lo, dg));
    need = v && ((med - m) < GAPT);
    nr = v ? (cv + m) : BIGF;
}
__device__ __forceinline__ void cell_exact(float a, float up, float dg, float cv,
                                           bool v, float& nr) {
    float lo = fminf(a, up), hi = fmaxf(a, up);
    float m = fminf(lo, dg);
    float med = fminf(hi, fmaxf(lo, dg));
    float mx = fmaxf(hi, dg);
    float e = 1.f + ex2f((m - med) * KS) + ex2f((m - mx) * KS);
    float r = cv + m - GLN2 * lg2f(e);
    nr = v ? r : BIGF;
}

__global__ __launch_bounds__(256) void dp_kernel() {
    const int b = blockIdx.x;
    const int tid = threadIdx.x;
    const int w = tid >> 5;
    const int lane = tid & 31;

    __shared__ float s_edge[2][8];
    if (tid < 16) ((float*)s_edge)[tid] = BIGF;
    __syncthreads();

    const int I = 4 * tid + 1;                    // first row (1-based)
    const float* base = g_costd + (size_t)b * 2047 * 1024 + 4 * tid;
    // slab row for diagonal d is (d-2); rows valid 0..2046

    float rp0 = BIGF, rp1 = BIGF, rp2 = BIGF, rp3 = BIGF;
    float qp0 = BIGF, qp1 = BIGF, qp2 = BIGF, qp3 = BIGF;
    // pu = previous diagonal's post-override u_sh; seeds R[0][0]=0 at d=2
    float pu = (w == 0 && lane == 0) ? 0.f : BIGF;

    const int wlo = 128 * w + 2;
    const int whi = 128 * w + 128 + TT;

    float4 cur[4], nxt[4];
    #pragma unroll
    for (int k = 0; k < 4; k++)
        cur[k] = *(const float4*)(base + (size_t)k * 1024);          // diags 2..5
    #pragma unroll
    for (int k = 0; k < 4; k++)
        nxt[k] = *(const float4*)(base + (size_t)(4 + k) * 1024);    // diags 6..9

    for (int d0 = 2; d0 <= 2046; d0 += 4) {
        // prefetch diagonals d0+8 .. d0+11 (rows d0+6 .. d0+9, clamped)
        float4 nn[4];
        #pragma unroll
        for (int k = 0; k < 4; k++) {
            int ri = d0 + 6 + k;
            if (ri > 2046) ri = 2046;
            nn[k] = *(const float4*)(base + (size_t)ri * 1024);
        }

        #pragma unroll
        for (int k = 0; k < 4; k++) {
            int d = d0 + k;
            if (d <= 2048) {
                bool act = (d >= wlo) && (d <= whi);
                float u_sh = __shfl_up_sync(0xFFFFFFFFu, rp3, 1);
                if (lane == 0)
                    u_sh = (w == 0) ? BIGF : s_edge[(d - 1) & 1][w - 1];
                float g_sh = pu;
                pu = u_sh;

                int jm1 = d - I - 1;
                float nr0, nr1, nr2, nr3;
                bool n0 = false, n1 = false, n2 = false, n3 = false;
                if (act) {
                    cell_fast(rp0, u_sh, g_sh, cur[k].x, (unsigned)jm1 < 1024u, nr0, n0);
                    cell_fast(rp1, rp0, qp0, cur[k].y, (unsigned)(jm1 - 1) < 1024u, nr1, n1);
                    cell_fast(rp2, rp1, qp1, cur[k].z, (unsigned)(jm1 - 2) < 1024u, nr2, n2);
                    cell_fast(rp3, rp2, qp2, cur[k].w, (unsigned)(jm1 - 3) < 1024u, nr3, n3);
                }
                if (__any_sync(0xFFFFFFFFu, (n0 | n1 | n2 | n3))) {
                    if (act) {   // warp-uniform; exact recompute of all 4 cells
                        cell_exact(rp0, u_sh, g_sh, cur[k].x, (unsigned)jm1 < 1024u, nr0);
                        cell_exact(rp1, rp0, qp0, cur[k].y, (unsigned)(jm1 - 1) < 1024u, nr1);
                        cell_exact(rp2, rp1, qp1, cur[k].z, (unsigned)(jm1 - 2) < 1024u, nr2);
                        cell_exact(rp3, rp2, qp2, cur[k].w, (unsigned)(jm1 - 3) < 1024u, nr3);
                    }
                }
                if (act) {
                    qp0 = rp0; qp1 = rp1; qp2 = rp2; qp3 = rp3;
                    rp0 = nr0; rp1 = nr1; rp2 = nr2; rp3 = nr3;
                }
                if (lane == 31) s_edge[d & 1][w] = rp3;
                __syncthreads();
            }
        }

        #pragma unroll
        for (int k = 0; k < 4; k++) { cur[k] = nxt[k]; nxt[k] = nn[k]; }
    }

    if (tid == 255) g_partial[b] = rp3;   // R[T][T]
}

// ---------------------------------------------------------------------------
// Kernel 3: deterministic sum of the 16 per-batch distances.
// ---------------------------------------------------------------------------
__global__ void sum_kernel(float* out) {
    if (threadIdx.x == 0) {
        float s = 0.f;
        #pragma unroll
        for (int b = 0; b < BB; b++) s += g_partial[b];
        out[0] = s;
    }
}

extern "C" void kernel_launch(void* const* d_in, const int* in_sizes, int n_in,
                              void* d_out, int out_size) {
    const float* x = (const float*)d_in[0];
    const float* y = (const float*)d_in[1];
    float* out = (float*)d_out;

    norms_kernel<<<4096, 256>>>(x, y);
    cost_kernel<<<dim3(8, 8, BB), 256>>>(x, y);
    dp_kernel<<<BB, 256>>>();
    sum_kernel<<<1, 32>>>(out);
}

// round 8
// speedup vs baseline: 3.3244x; 1.0389x over previous
#include <cuda_runtime.h>
#include <cstddef>

#define TT 1024
#define BB 16
#define CC 64
#define BIGF 1e10f
// 1/(gamma*ln2), gamma = 0.01
#define KS 144.2695040888963f
// gamma*ln2
#define GLN2 0.006931471805599453f
// (med - min) threshold below which exp terms matter (16 / KS)
#define GAPT 0.11090354888959125f

// Scratch (device globals: allocation-free rule)
// Anti-diagonal-major cost: entry (i,j) 1-based lives at [b][(i+j)-2][i-1].
__device__ float g_costd[(size_t)BB * 2047 * 1024];   // 134 MB
__device__ float g_nx[BB * TT];
__device__ float g_ny[BB * TT];
__device__ float g_partial[BB];

__device__ __forceinline__ float ex2f(float x) {
    float y;
    asm("ex2.approx.ftz.f32 %0, %1;" : "=f"(y) : "f"(x));
    return y;
}
__device__ __forceinline__ float lg2f(float x) {
    float y;
    asm("lg2.approx.ftz.f32 %0, %1;" : "=f"(y) : "f"(x));
    return y;
}

// ---------------------------------------------------------------------------
// Kernel 0: row norms  ||x_i||^2, ||y_j||^2  (one warp per row)
// ---------------------------------------------------------------------------
__global__ void norms_kernel(const float* __restrict__ x,
                             const float* __restrict__ y) {
    int gwarp = (blockIdx.x * blockDim.x + threadIdx.x) >> 5;
    int lane = threadIdx.x & 31;
    const int nrows = BB * TT;
    if (gwarp >= 2 * nrows) return;
    const float* src = (gwarp < nrows) ? x : y;
    float* dst = (gwarp < nrows) ? g_nx : g_ny;
    int row = (gwarp < nrows) ? gwarp : (gwarp - nrows);
    float v0 = src[(size_t)row * CC + lane];
    float v1 = src[(size_t)row * CC + 32 + lane];
    float s = v0 * v0 + v1 * v1;
    #pragma unroll
    for (int o = 16; o; o >>= 1) s += __shfl_xor_sync(0xFFFFFFFFu, s, o);
    if (lane == 0) dst[row] = s;
}

// ---------------------------------------------------------------------------
// Kernel 1: cost tile 128x128 per CTA (8x8 regs/thread), then scatter the
// tile to anti-diagonal-major g_costd via smem (2 phases of 64 rows).
// ---------------------------------------------------------------------------
#define PITCH 132
__global__ __launch_bounds__(256) void cost_kernel(const float* __restrict__ x,
                                                   const float* __restrict__ y) {
    __shared__ float sbuf[8448];   // union: xs[32*132] + ys[32*132] | tile 64*132
    float* xs = sbuf;              // [kk][row] -> kk*132 + row
    float* ys = sbuf + 4224;

    int b = blockIdx.z;
    int I0 = blockIdx.y * 128;
    int J0 = blockIdx.x * 128;
    int tid = threadIdx.x;
    int tx = tid & 15;
    int ty = tid >> 4;
    int w = tid >> 5;
    int lane = tid & 31;

    const float* xb = x + ((size_t)b * TT + I0) * CC;
    const float* yb = y + ((size_t)b * TT + J0) * CC;

    float acc[8][8];
    #pragma unroll
    for (int r = 0; r < 8; r++)
        #pragma unroll
        for (int s = 0; s < 8; s++) acc[r][s] = 0.f;

    for (int k0 = 0; k0 < CC; k0 += 32) {
        __syncthreads();
        #pragma unroll
        for (int e = 0; e < 4096; e += 256) {
            int idx = e + tid;
            int row = idx >> 5;
            int kk = idx & 31;
            xs[kk * 132 + row] = xb[(size_t)row * CC + k0 + kk];
            ys[kk * 132 + row] = yb[(size_t)row * CC + k0 + kk];
        }
        __syncthreads();
        #pragma unroll
        for (int kk = 0; kk < 32; kk++) {
            float4 xv0 = *(const float4*)&xs[kk * 132 + ty * 8];
            float4 xv1 = *(const float4*)&xs[kk * 132 + ty * 8 + 4];
            float4 yv0 = *(const float4*)&ys[kk * 132 + tx * 8];
            float4 yv1 = *(const float4*)&ys[kk * 132 + tx * 8 + 4];
            float xr[8] = {xv0.x, xv0.y, xv0.z, xv0.w, xv1.x, xv1.y, xv1.z, xv1.w};
            float yr[8] = {yv0.x, yv0.y, yv0.z, yv0.w, yv1.x, yv1.y, yv1.z, yv1.w};
            #pragma unroll
            for (int r = 0; r < 8; r++)
                #pragma unroll
                for (int s = 0; s < 8; s++)
                    acc[r][s] = fmaf(xr[r], yr[s], acc[r][s]);
        }
    }

    float x2[8], y2[8];
    #pragma unroll
    for (int r = 0; r < 8; r++) x2[r] = g_nx[b * TT + I0 + ty * 8 + r];
    #pragma unroll
    for (int s = 0; s < 8; s++) y2[s] = g_ny[b * TT + J0 + tx * 8 + s];

    float* slab = g_costd + (size_t)b * 2047 * 1024;

    #pragma unroll
    for (int ph = 0; ph < 2; ph++) {
        __syncthreads();
        if ((ty >> 3) == ph) {
            int rl = (ty & 7) * 8;
            #pragma unroll
            for (int r = 0; r < 8; r++) {
                float4 o0, o1;
                o0.x = fmaf(-2.f, acc[r][0], x2[r] + y2[0]);
                o0.y = fmaf(-2.f, acc[r][1], x2[r] + y2[1]);
                o0.z = fmaf(-2.f, acc[r][2], x2[r] + y2[2]);
                o0.w = fmaf(-2.f, acc[r][3], x2[r] + y2[3]);
                o1.x = fmaf(-2.f, acc[r][4], x2[r] + y2[4]);
                o1.y = fmaf(-2.f, acc[r][5], x2[r] + y2[5]);
                o1.z = fmaf(-2.f, acc[r][6], x2[r] + y2[6]);
                o1.w = fmaf(-2.f, acc[r][7], x2[r] + y2[7]);
                *(float4*)&sbuf[(rl + r) * PITCH + tx * 8] = o0;
                *(float4*)&sbuf[(rl + r) * PITCH + tx * 8 + 4] = o1;
            }
        }
        __syncthreads();
        int Dlo = ph * 64, Dhi = ph * 64 + 190;
        for (int D = Dlo + w; D <= Dhi; D += 8) {
            int rlo = ph * 64;      if (D - 127 > rlo) rlo = D - 127;
            int rhi = ph * 64 + 63; if (D < rhi) rhi = D;
            int len = rhi - rlo + 1;
            if (len <= 0) continue;
            float* gout = slab + (size_t)(I0 + J0 + D) * 1024 + I0 + rlo;
            int sb = (rlo - ph * 64) * PITCH + (D - rlo);
            for (int k = lane; k < len; k += 32)
                gout[k] = sbuf[sb + k * (PITCH - 1)];
        }
    }
}

// ---------------------------------------------------------------------------
// Kernel 2: soft-DTW wavefront, warp-skewed rounds.
// Warp w processes diagonals 4(r-w)+2 .. +5 in round r -> ONE __syncthreads
// per 4 diagonals (519 rounds). Cross-warp edges via 16-slot smem ring per
// warp: same-round writes hit slots +4..+7 (mod 16) vs reads -1..+2 ->
// disjoint, race-free; barrier makes prior-round writes visible.
// ---------------------------------------------------------------------------
__device__ __forceinline__ void cell_fast(float a, float up, float dg, float cv,
                                          bool v, float& nr, bool& need) {
    float lo = fminf(a, up), hi = fmaxf(a, up);
    float m = fminf(lo, dg);
    float med = fminf(hi, fmaxf(lo, dg));
    need = v && ((med - m) < GAPT);
    nr = v ? (cv + m) : BIGF;
}
__device__ __forceinline__ void cell_exact(float a, float up, float dg, float cv,
                                           bool v, float& nr) {
    float lo = fminf(a, up), hi = fmaxf(a, up);
    float m = fminf(lo, dg);
    float med = fminf(hi, fmaxf(lo, dg));
    float mx = fmaxf(hi, dg);
    float e = 1.f + ex2f((m - med) * KS) + ex2f((m - mx) * KS);
    float r = cv + m - GLN2 * lg2f(e);
    nr = v ? r : BIGF;
}

__global__ __launch_bounds__(256) void dp_kernel() {
    const int b = blockIdx.x;
    const int tid = threadIdx.x;
    const int w = tid >> 5;
    const int lane = tid & 31;

    __shared__ float s_edge[8][16];   // per-warp edge ring, slot = diag & 15
    if (tid < 128) ((float*)s_edge)[tid] = BIGF;
    __syncthreads();

    const int I = 4 * tid + 1;                    // first row (1-based)
    const float* base = g_costd + (size_t)b * 2047 * 1024 + 4 * tid;
    // slab row for diagonal d is (d-2); rows valid 0..2046

    float rp0 = BIGF, rp1 = BIGF, rp2 = BIGF, rp3 = BIGF;
    float qp0 = BIGF, qp1 = BIGF, qp2 = BIGF, qp3 = BIGF;
    // pu = previous diagonal's post-override u_sh; seeds R[0][0]=0 at d=2
    float pu = (w == 0 && lane == 0) ? 0.f : BIGF;

    const int wlo = 128 * w + 2;
    const int whi = 128 * w + 128 + TT;           // w=7 -> exactly 2048

    float4 cur[4], nxt[4];
    #pragma unroll
    for (int k = 0; k < 4; k++)
        cur[k] = *(const float4*)(base + (size_t)k * 1024);          // diags 2..5
    #pragma unroll
    for (int k = 0; k < 4; k++)
        nxt[k] = *(const float4*)(base + (size_t)(4 + k) * 1024);    // diags 6..9

    int rw = -w;   // r - w
    for (int r = 0; r < 519; ++r, ++rw) {
        if (rw >= 0) {
            int D = 4 * rw + 2;   // this warp's first diagonal this round
            // prefetch rows for round r+2: 4*rw+8 .. +11 (clamped)
            float4 nn[4];
            #pragma unroll
            for (int k = 0; k < 4; k++) {
                int ri = 4 * rw + 8 + k;
                if (ri > 2046) ri = 2046;
                nn[k] = *(const float4*)(base + (size_t)ri * 1024);
            }

            if (D <= whi && D + 3 >= wlo) {
                #pragma unroll
                for (int k = 0; k < 4; k++) {
                    int d = D + k;
                    bool act = (d >= wlo) && (d <= whi);
                    float u_sh = __shfl_up_sync(0xFFFFFFFFu, rp3, 1);
                    if (lane == 0)
                        u_sh = (w == 0) ? BIGF : s_edge[w - 1][(d - 1) & 15];
                    float g_sh = pu;
                    pu = u_sh;

                    int jm1 = d - I - 1;
                    float nr0, nr1, nr2, nr3;
                    bool n0 = false, n1 = false, n2 = false, n3 = false;
                    if (act) {
                        cell_fast(rp0, u_sh, g_sh, cur[k].x, (unsigned)jm1 < 1024u, nr0, n0);
                        cell_fast(rp1, rp0, qp0, cur[k].y, (unsigned)(jm1 - 1) < 1024u, nr1, n1);
                        cell_fast(rp2, rp1, qp1, cur[k].z, (unsigned)(jm1 - 2) < 1024u, nr2, n2);
                        cell_fast(rp3, rp2, qp2, cur[k].w, (unsigned)(jm1 - 3) < 1024u, nr3, n3);
                    }
                    if (__any_sync(0xFFFFFFFFu, (n0 | n1 | n2 | n3))) {
                        if (act) {   // warp-uniform; exact recompute of all 4 cells
                            cell_exact(rp0, u_sh, g_sh, cur[k].x, (unsigned)jm1 < 1024u, nr0);
                            cell_exact(rp1, rp0, qp0, cur[k].y, (unsigned)(jm1 - 1) < 1024u, nr1);
                            cell_exact(rp2, rp1, qp1, cur[k].z, (unsigned)(jm1 - 2) < 1024u, nr2);
                            cell_exact(rp3, rp2, qp2, cur[k].w, (unsigned)(jm1 - 3) < 1024u, nr3);
                        }
                    }
                    if (act) {
                        qp0 = rp0; qp1 = rp1; qp2 = rp2; qp3 = rp3;
                        rp0 = nr0; rp1 = nr1; rp2 = nr2; rp3 = nr3;
                    }
                    if (lane == 31) s_edge[w][d & 15] = rp3;
                }
            }

            #pragma unroll
            for (int k = 0; k < 4; k++) { cur[k] = nxt[k]; nxt[k] = nn[k]; }
        }
        __syncthreads();
    }

    if (tid == 255) g_partial[b] = rp3;   // R[T][T] (warp 7 ends at d=2048)
}

// ---------------------------------------------------------------------------
// Kernel 3: deterministic sum of the 16 per-batch distances.
// ---------------------------------------------------------------------------
__global__ void sum_kernel(float* out) {
    if (threadIdx.x == 0) {
        float s = 0.f;
        #pragma unroll
        for (int b = 0; b < BB; b++) s += g_partial[b];
        out[0] = s;
    }
}

extern "C" void kernel_launch(void* const* d_in, const int* in_sizes, int n_in,
                              void* d_out, int out_size) {
    const float* x = (const float*)d_in[0];
    const float* y = (const float*)d_in[1];
    float* out = (float*)d_out;

    norms_kernel<<<4096, 256>>>(x, y);
    cost_kernel<<<dim3(8, 8, BB), 256>>>(x, y);
    dp_kernel<<<BB, 256>>>();
    sum_kernel<<<1, 32>>>(out);
}